// round 6
// baseline (speedup 1.0000x reference)
#include <cuda_runtime.h>
#include <cuda_bf16.h>

#define NN 100000
#define DD 64
#define EMAX 1000000
#define GRID 148
#define TPB 256
#define CH 676            // ceil(NN/GRID); GRID*CH = 100048 >= NN

// ---------------- device scratch (no allocation allowed) ----------------
__device__ float g_h0[NN * DD];
__device__ float g_h1[NN * DD];
__device__ float g_agg[NN * DD];
__device__ int   g_deg[NN];
__device__ int   g_rowptr[NN + 1];
__device__ int   g_cursor[NN];
__device__ int   g_col[EMAX];
__device__ int   g_part[GRID];
__device__ int   g_boff[GRID];
__device__ unsigned g_arrive;   // zero-init; returns to 0 after every barrier
__device__ unsigned g_gen;      // monotonic generation counter (base-relative)

// ---------------- software grid barrier (all GRID blocks co-resident) ----------------
__device__ __forceinline__ void gsync(unsigned& target) {
    __syncthreads();
    if (threadIdx.x == 0) {
        __threadfence();                       // make phase data visible
        unsigned t = atomicAdd(&g_arrive, 1u);
        if (t == GRID - 1) {
            g_arrive = 0;
            __threadfence();                   // reset visible before release
            *(volatile unsigned*)&g_gen = target;
        } else {
            unsigned v;
            do {
                __nanosleep(32);
                v = *(volatile unsigned*)&g_gen;
            } while (v != target);
            __threadfence();                   // acquire
        }
    }
    __syncthreads();
    target += 1;
}

struct SmemGemm { float sh[2][8][DD]; float sa[2][8][DD]; };
union Smem {
    int ps[TPB];
    SmemGemm g;
    float lin[2][4][DD];
};

__global__ __launch_bounds__(TPB, 1) void k_all(
    const float* __restrict__ x,
    const int* __restrict__ src, const int* __restrict__ dst,
    const int* __restrict__ ea, const int* __restrict__ eb,
    const float* __restrict__ W_lin, const float* __restrict__ b_lin,
    const float* __restrict__ Wl1, const float* __restrict__ bl1, const float* __restrict__ Wr1,
    const float* __restrict__ Wl2, const float* __restrict__ bl2, const float* __restrict__ Wr2,
    float* __restrict__ preds,
    int N, int E, int EL)
{
    __shared__ __align__(16) Smem smem;
    const int bid = blockIdx.x;
    const int tid = threadIdx.x;
    unsigned target = *(volatile unsigned*)&g_gen + 1;   // base-relative

    // ---------- P0: zero deg ----------
    for (int i = bid * TPB + tid; i < N; i += GRID * TPB) g_deg[i] = 0;
    gsync(target);

    // ---------- P1: histogram ----------
    for (int e = bid * TPB + tid; e < E; e += GRID * TPB)
        atomicAdd(&g_deg[dst[e]], 1);
    gsync(target);

    // ---------- P2: per-block partial sums over chunk ----------
    {
        int cb = bid * CH;
        int ce = min(cb + CH, N);
        int s = 0;
        for (int i = cb + tid; i < ce; i += TPB) s += g_deg[i];
        smem.ps[tid] = s;
        __syncthreads();
        for (int d = 128; d > 0; d >>= 1) {
            if (tid < d) smem.ps[tid] += smem.ps[tid + d];
            __syncthreads();
        }
        if (tid == 0) g_part[bid] = smem.ps[0];
    }
    gsync(target);

    // ---------- P3: block 0 scans the GRID partials ----------
    if (bid == 0) {
        int v = (tid < GRID) ? g_part[tid] : 0;
        smem.ps[tid] = v;
        __syncthreads();
        for (int d = 1; d < TPB; d <<= 1) {
            int u = (tid >= d) ? smem.ps[tid - d] : 0;
            __syncthreads();
            smem.ps[tid] += u;
            __syncthreads();
        }
        if (tid < GRID) g_boff[tid] = smem.ps[tid] - v;   // exclusive
        if (tid == GRID - 1) g_rowptr[N] = smem.ps[tid];
    }
    gsync(target);

    // ---------- P4: local exclusive scan -> rowptr/cursor ----------
    {
        int cb = bid * CH;
        int lim = min(cb + CH, N);
        int i0 = cb + tid * 3;
        int v0 = (i0 < lim) ? g_deg[i0] : 0;
        int v1 = (i0 + 1 < lim) ? g_deg[i0 + 1] : 0;
        int v2 = (i0 + 2 < lim) ? g_deg[i0 + 2] : 0;
        int tsum = v0 + v1 + v2;
        smem.ps[tid] = tsum;
        __syncthreads();
        for (int d = 1; d < TPB; d <<= 1) {
            int u = (tid >= d) ? smem.ps[tid - d] : 0;
            __syncthreads();
            smem.ps[tid] += u;
            __syncthreads();
        }
        int off = g_boff[bid] + smem.ps[tid] - tsum;
        if (i0 < lim)     { g_rowptr[i0] = off;     g_cursor[i0] = off;     off += v0; }
        if (i0 + 1 < lim) { g_rowptr[i0 + 1] = off; g_cursor[i0 + 1] = off; off += v1; }
        if (i0 + 2 < lim) { g_rowptr[i0 + 2] = off; g_cursor[i0 + 2] = off; }
    }
    gsync(target);

    // ---------- P5: scatter ----------
    for (int e = bid * TPB + tid; e < E; e += GRID * TPB) {
        int d = dst[e];
        int p = atomicAdd(&g_cursor[d], 1);
        g_col[p] = src[e];
    }
    gsync(target);

    // ---------- P6: node linear  h0 = x @ W^T + b ----------
    {
        int g = tid >> 6;
        int j = tid & 63;
        float w[DD];
#pragma unroll
        for (int k = 0; k < DD; k += 4) {
            float4 a = *(const float4*)&W_lin[j * DD + k];
            w[k] = a.x; w[k + 1] = a.y; w[k + 2] = a.z; w[k + 3] = a.w;
        }
        float bj = b_lin[j];
        int stride = GRID * 4;
        int i0 = bid * 4 + g;
        float hv = (i0 < N) ? x[i0 * DD + j] : 0.f;
        int buf = 0;
        for (int base = bid * 4; base < N; base += stride) {
            int i = base + g;
            smem.lin[buf][g][j] = hv;
            __syncthreads();
            int inx = i + stride;
            hv = (inx < N) ? x[inx * DD + j] : 0.f;
            if (i < N) {
                const float4* h4 = (const float4*)smem.lin[buf][g];
                float a0 = 0.f, a1 = 0.f, a2 = 0.f, a3 = 0.f;
#pragma unroll
                for (int k4 = 0; k4 < 16; k4++) {
                    float4 hvv = h4[k4];
                    a0 += hvv.x * w[k4 * 4 + 0];
                    a1 += hvv.y * w[k4 * 4 + 1];
                    a2 += hvv.z * w[k4 * 4 + 2];
                    a3 += hvv.w * w[k4 * 4 + 3];
                }
                g_h0[i * DD + j] = (a0 + a1) + (a2 + a3) + bj;
            }
            buf ^= 1;
            __syncthreads();
        }
    }
    gsync(target);

    // ============ two SAGE layers ============
#pragma unroll 1
    for (int layer = 0; layer < 2; layer++) {
        const float* hin  = (layer == 0) ? g_h0 : g_h1;
        float*       hout = (layer == 0) ? g_h1 : g_h0;
        const float* Wl = (layer == 0) ? Wl1 : Wl2;
        const float* bl = (layer == 0) ? bl1 : bl2;
        const float* Wr = (layer == 0) ? Wr1 : Wr2;
        int do_relu = (layer == 0);

        // ---------- agg: half-warp per node, grid-stride ----------
        {
            int hw = bid * 16 + (tid >> 4);
            int l = tid & 15;
            for (int node = hw; node < N; node += GRID * 16) {
                int s = g_rowptr[node];
                int e = g_rowptr[node + 1];
                float ax = 0.f, ay = 0.f, az = 0.f, aw = 0.f;
                int nn = s;
                for (; nn + 4 <= e; nn += 4) {
                    int c0 = g_col[nn], c1 = g_col[nn + 1];
                    int c2 = g_col[nn + 2], c3 = g_col[nn + 3];
                    float4 v0 = ((const float4*)(hin + c0 * DD))[l];
                    float4 v1 = ((const float4*)(hin + c1 * DD))[l];
                    float4 v2 = ((const float4*)(hin + c2 * DD))[l];
                    float4 v3 = ((const float4*)(hin + c3 * DD))[l];
                    ax += (v0.x + v1.x) + (v2.x + v3.x);
                    ay += (v0.y + v1.y) + (v2.y + v3.y);
                    az += (v0.z + v1.z) + (v2.z + v3.z);
                    aw += (v0.w + v1.w) + (v2.w + v3.w);
                }
                for (; nn < e; nn++) {
                    float4 v = ((const float4*)(hin + g_col[nn] * DD))[l];
                    ax += v.x; ay += v.y; az += v.z; aw += v.w;
                }
                float inv = (e > s) ? 1.f / (float)(e - s) : 0.f;
                ((float4*)(g_agg + node * DD))[l] =
                    make_float4(ax * inv, ay * inv, az * inv, aw * inv);
            }
        }
        gsync(target);

        // ---------- gemm: hout = agg@Wl^T + bl + hin@Wr^T ----------
        {
            int g = tid >> 6;
            int j = tid & 63;
            float wl[DD], wr[DD];
#pragma unroll
            for (int k = 0; k < DD; k += 4) {
                float4 a = *(const float4*)&Wl[j * DD + k];
                wl[k] = a.x; wl[k + 1] = a.y; wl[k + 2] = a.z; wl[k + 3] = a.w;
                float4 c = *(const float4*)&Wr[j * DD + k];
                wr[k] = c.x; wr[k + 1] = c.y; wr[k + 2] = c.z; wr[k + 3] = c.w;
            }
            float bj = bl[j];
            int stride = GRID * 8;
            int iA0 = bid * 8 + g;
            int iB0 = iA0 + 4;
            float hvA = 0.f, avA = 0.f, hvB = 0.f, avB = 0.f;
            if (iA0 < N) { hvA = hin[iA0 * DD + j]; avA = g_agg[iA0 * DD + j]; }
            if (iB0 < N) { hvB = hin[iB0 * DD + j]; avB = g_agg[iB0 * DD + j]; }
            int buf = 0;
            for (int base = bid * 8; base < N; base += stride) {
                int iA = base + g;
                int iB = iA + 4;
                smem.g.sh[buf][g][j] = hvA;
                smem.g.sa[buf][g][j] = avA;
                smem.g.sh[buf][g + 4][j] = hvB;
                smem.g.sa[buf][g + 4][j] = avB;
                __syncthreads();
                int nA = iA + stride, nB = iB + stride;
                if (nA < N) { hvA = hin[nA * DD + j]; avA = g_agg[nA * DD + j]; }
                else        { hvA = 0.f; avA = 0.f; }
                if (nB < N) { hvB = hin[nB * DD + j]; avB = g_agg[nB * DD + j]; }
                else        { hvB = 0.f; avB = 0.f; }

                const float4* h4A = (const float4*)smem.g.sh[buf][g];
                const float4* a4A = (const float4*)smem.g.sa[buf][g];
                const float4* h4B = (const float4*)smem.g.sh[buf][g + 4];
                const float4* a4B = (const float4*)smem.g.sa[buf][g + 4];
                float A0 = 0.f, A1 = 0.f, A2 = 0.f, A3 = 0.f;
                float B0 = 0.f, B1 = 0.f, B2 = 0.f, B3 = 0.f;
#pragma unroll
                for (int k4 = 0; k4 < 16; k4++) {
                    float4 aA = a4A[k4];
                    float4 hA = h4A[k4];
                    float4 aB = a4B[k4];
                    float4 hB = h4B[k4];
                    float w0 = wl[k4 * 4 + 0], w1 = wl[k4 * 4 + 1];
                    float w2 = wl[k4 * 4 + 2], w3 = wl[k4 * 4 + 3];
                    float r0 = wr[k4 * 4 + 0], r1 = wr[k4 * 4 + 1];
                    float r2 = wr[k4 * 4 + 2], r3 = wr[k4 * 4 + 3];
                    A0 += aA.x * w0; A1 += aA.y * w1; A2 += aA.z * w2; A3 += aA.w * w3;
                    A0 += hA.x * r0; A1 += hA.y * r1; A2 += hA.z * r2; A3 += hA.w * r3;
                    B0 += aB.x * w0; B1 += aB.y * w1; B2 += aB.z * w2; B3 += aB.w * w3;
                    B0 += hB.x * r0; B1 += hB.y * r1; B2 += hB.z * r2; B3 += hB.w * r3;
                }
                if (iA < N) {
                    float r = (A0 + A1) + (A2 + A3) + bj;
                    if (do_relu) r = fmaxf(r, 0.f);
                    hout[iA * DD + j] = r;
                }
                if (iB < N) {
                    float r = (B0 + B1) + (B2 + B3) + bj;
                    if (do_relu) r = fmaxf(r, 0.f);
                    hout[iB * DD + j] = r;
                }
                buf ^= 1;
                __syncthreads();
            }
        }
        gsync(target);
    }

    // ---------- edge dot product (h0 holds final embeddings) ----------
    {
        int w = bid * 8 + (tid >> 5);
        int lane = tid & 31;
        for (int e = w; e < EL; e += GRID * 8) {
            int a = ea[e];
            int b = eb[e];
            float2 va = ((const float2*)(g_h0 + a * DD))[lane];
            float2 vb = ((const float2*)(g_h0 + b * DD))[lane];
            float p = va.x * vb.x + va.y * vb.y;
#pragma unroll
            for (int o = 16; o > 0; o >>= 1) p += __shfl_down_sync(0xffffffffu, p, o);
            if (lane == 0) preds[e] = p;
        }
    }
}

// ---------------- launch ----------------
extern "C" void kernel_launch(void* const* d_in, const int* in_sizes, int n_in,
                              void* d_out, int out_size) {
    const float* x     = (const float*)d_in[0];
    const int*   ei    = (const int*)d_in[1];
    const int*   eli   = (const int*)d_in[2];
    const float* W_lin = (const float*)d_in[3];
    const float* b_lin = (const float*)d_in[4];
    const float* Wl1   = (const float*)d_in[5];
    const float* bl1   = (const float*)d_in[6];
    const float* Wr1   = (const float*)d_in[7];
    const float* Wl2   = (const float*)d_in[8];
    const float* bl2   = (const float*)d_in[9];
    const float* Wr2   = (const float*)d_in[10];

    int N  = in_sizes[0] / DD;      // 100000
    int E  = in_sizes[1] / 2;       // 1000000
    int EL = in_sizes[2] / 2;       // 200000

    const int* src = ei;            // edge_index[0] = source
    const int* dst = ei + E;        // edge_index[1] = target
    const int* ea  = eli;
    const int* eb  = eli + EL;

    float* preds = (float*)d_out;

    k_all<<<GRID, TPB>>>(x, src, dst, ea, eb,
                         W_lin, b_lin, Wl1, bl1, Wr1, Wl2, bl2, Wr2,
                         preds, N, E, EL);
}

// round 7
// speedup vs baseline: 1.1880x; 1.1880x over previous
#include <cuda_runtime.h>
#include <cuda_bf16.h>

#define NN 100000
#define DD 64
#define EMAX 1000000
#define SCAN_CHUNK 512   // blocks = ceil(NN/512) = 196 <= 256

// ---------------- device scratch (no allocation allowed) ----------------
__device__ float g_h0[NN * DD];
__device__ float g_h1[NN * DD];
__device__ float g_agg[NN * DD];
__device__ int   g_deg[NN];
__device__ int   g_rowptr[NN + 1];
__device__ int   g_cursor[NN];
__device__ int   g_col[EMAX];
__device__ int   g_part[256];
__device__ int   g_boff[256];

// ---------------- CSR build ----------------
__global__ void k_hist(const int* __restrict__ dst, int* __restrict__ deg, int E) {
    for (int e = blockIdx.x * blockDim.x + threadIdx.x; e < E; e += gridDim.x * blockDim.x)
        atomicAdd(&deg[dst[e]], 1);
}

__global__ void k_scan1(const int* __restrict__ deg, int* __restrict__ part, int n) {
    __shared__ int ps[256];
    int b = blockIdx.x;
    int t = threadIdx.x;
    int base = b * SCAN_CHUNK + t * 2;
    int s = 0;
    if (base < n)     s += deg[base];
    if (base + 1 < n) s += deg[base + 1];
    ps[t] = s;
    __syncthreads();
    for (int d = 128; d > 0; d >>= 1) {
        if (t < d) ps[t] += ps[t + d];
        __syncthreads();
    }
    if (t == 0) part[b] = ps[0];
}

__global__ void k_scan2(const int* __restrict__ part, int* __restrict__ boff,
                        int* __restrict__ rowptr, int n, int nblk) {
    __shared__ int ps[256];
    int t = threadIdx.x;
    ps[t] = (t < nblk) ? part[t] : 0;
    __syncthreads();
    for (int d = 1; d < 256; d <<= 1) {
        int v = (t >= d) ? ps[t - d] : 0;
        __syncthreads();
        ps[t] += v;
        __syncthreads();
    }
    boff[t] = (t == 0) ? 0 : ps[t - 1];
    if (t == 255) rowptr[n] = ps[255];
}

__global__ void k_scan3(const int* __restrict__ deg, const int* __restrict__ boff,
                        int* __restrict__ rowptr, int* __restrict__ cursor, int n) {
    __shared__ int ps[256];
    int b = blockIdx.x;
    int t = threadIdx.x;
    int base = b * SCAN_CHUNK + t * 2;
    int d0 = (base < n) ? deg[base] : 0;
    int d1 = (base + 1 < n) ? deg[base + 1] : 0;
    ps[t] = d0 + d1;
    __syncthreads();
    for (int d = 1; d < 256; d <<= 1) {
        int v = (t >= d) ? ps[t - d] : 0;
        __syncthreads();
        ps[t] += v;
        __syncthreads();
    }
    int off = boff[b] + ((t == 0) ? 0 : ps[t - 1]);
    if (base < n)     { rowptr[base] = off;          cursor[base] = off; }
    if (base + 1 < n) { rowptr[base + 1] = off + d0; cursor[base + 1] = off + d0; }
}

__global__ void k_scatter(const int* __restrict__ src, const int* __restrict__ dst,
                          int* __restrict__ cursor, int* __restrict__ col, int E) {
    for (int e = blockIdx.x * blockDim.x + threadIdx.x; e < E; e += gridDim.x * blockDim.x) {
        int d = dst[e];
        int p = atomicAdd(&cursor[d], 1);
        col[p] = src[e];
    }
}

// ---------------- mean aggregation: half-warp per node, float4 lanes, 8-deep MLP ----------------
__global__ __launch_bounds__(256) void k_agg(
    const float* __restrict__ h, const int* __restrict__ rowptr,
    const int* __restrict__ col, float* __restrict__ agg, int n) {
    int node = (blockIdx.x * blockDim.x + threadIdx.x) >> 4;
    int l = threadIdx.x & 15;
    if (node >= n) return;
    int s = rowptr[node];
    int e = rowptr[node + 1];
    float ax = 0.f, ay = 0.f, az = 0.f, aw = 0.f;
    int nn = s;
    for (; nn + 8 <= e; nn += 8) {
        int c0 = col[nn],     c1 = col[nn + 1], c2 = col[nn + 2], c3 = col[nn + 3];
        int c4 = col[nn + 4], c5 = col[nn + 5], c6 = col[nn + 6], c7 = col[nn + 7];
        float4 v0 = ((const float4*)(h + c0 * DD))[l];
        float4 v1 = ((const float4*)(h + c1 * DD))[l];
        float4 v2 = ((const float4*)(h + c2 * DD))[l];
        float4 v3 = ((const float4*)(h + c3 * DD))[l];
        float4 v4 = ((const float4*)(h + c4 * DD))[l];
        float4 v5 = ((const float4*)(h + c5 * DD))[l];
        float4 v6 = ((const float4*)(h + c6 * DD))[l];
        float4 v7 = ((const float4*)(h + c7 * DD))[l];
        ax += ((v0.x + v1.x) + (v2.x + v3.x)) + ((v4.x + v5.x) + (v6.x + v7.x));
        ay += ((v0.y + v1.y) + (v2.y + v3.y)) + ((v4.y + v5.y) + (v6.y + v7.y));
        az += ((v0.z + v1.z) + (v2.z + v3.z)) + ((v4.z + v5.z) + (v6.z + v7.z));
        aw += ((v0.w + v1.w) + (v2.w + v3.w)) + ((v4.w + v5.w) + (v6.w + v7.w));
    }
    for (; nn + 4 <= e; nn += 4) {
        int c0 = col[nn], c1 = col[nn + 1], c2 = col[nn + 2], c3 = col[nn + 3];
        float4 v0 = ((const float4*)(h + c0 * DD))[l];
        float4 v1 = ((const float4*)(h + c1 * DD))[l];
        float4 v2 = ((const float4*)(h + c2 * DD))[l];
        float4 v3 = ((const float4*)(h + c3 * DD))[l];
        ax += (v0.x + v1.x) + (v2.x + v3.x);
        ay += (v0.y + v1.y) + (v2.y + v3.y);
        az += (v0.z + v1.z) + (v2.z + v3.z);
        aw += (v0.w + v1.w) + (v2.w + v3.w);
    }
    for (; nn < e; nn++) {
        float4 v = ((const float4*)(h + col[nn] * DD))[l];
        ax += v.x; ay += v.y; az += v.z; aw += v.w;
    }
    float inv = (e > s) ? 1.f / (float)(e - s) : 0.f;
    ((float4*)(agg + node * DD))[l] = make_float4(ax * inv, ay * inv, az * inv, aw * inv);
}

// ---------------- node linear: out = x @ W^T + b (double-buffered) ----------------
__global__ __launch_bounds__(256, 2) void k_lin(
    const float* __restrict__ x, const float* __restrict__ W,
    const float* __restrict__ b, float* __restrict__ out, int n) {
    __shared__ __align__(16) float sh[2][4][DD];
    int tid = threadIdx.x;
    int g = tid >> 6;
    int j = tid & 63;

    float w[DD];
#pragma unroll
    for (int k = 0; k < DD; k += 4) {
        float4 a = *(const float4*)&W[j * DD + k];
        w[k] = a.x; w[k + 1] = a.y; w[k + 2] = a.z; w[k + 3] = a.w;
    }
    float bj = b[j];

    int stride = gridDim.x * 4;
    int i0 = blockIdx.x * 4 + g;
    float hv = 0.f;
    if (i0 < n) hv = x[i0 * DD + j];
    int buf = 0;
    for (int base = blockIdx.x * 4; base < n; base += stride) {
        int i = base + g;
        sh[buf][g][j] = hv;
        __syncthreads();
        int inx = i + stride;
        hv = (inx < n) ? x[inx * DD + j] : 0.f;
        if (i < n) {
            const float4* h4 = (const float4*)sh[buf][g];
            float a0 = 0.f, a1 = 0.f, a2 = 0.f, a3 = 0.f;
#pragma unroll
            for (int k4 = 0; k4 < 16; k4++) {
                float4 hvv = h4[k4];
                a0 += hvv.x * w[k4 * 4 + 0];
                a1 += hvv.y * w[k4 * 4 + 1];
                a2 += hvv.z * w[k4 * 4 + 2];
                a3 += hvv.w * w[k4 * 4 + 3];
            }
            out[i * DD + j] = (a0 + a1) + (a2 + a3) + bj;
        }
        buf ^= 1;
    }
}

// ---------------- dense SAGE transform: out = agg@Wl^T + bl + h@Wr^T ----------------
// 16 nodes per block-iteration; each thread computes col j for 4 nodes.
__global__ __launch_bounds__(256, 1) void k_gemm(
    const float* __restrict__ h, const float* __restrict__ agg,
    const float* __restrict__ Wl, const float* __restrict__ bl,
    const float* __restrict__ Wr, float* __restrict__ out, int n, int do_relu) {
    __shared__ __align__(16) float sh[2][16][DD];
    __shared__ __align__(16) float sa[2][16][DD];
    int tid = threadIdx.x;
    int g = tid >> 6;       // 0..3
    int j = tid & 63;

    float wl[DD], wr[DD];
#pragma unroll
    for (int k = 0; k < DD; k += 4) {
        float4 a = *(const float4*)&Wl[j * DD + k];
        wl[k] = a.x; wl[k + 1] = a.y; wl[k + 2] = a.z; wl[k + 3] = a.w;
        float4 c = *(const float4*)&Wr[j * DD + k];
        wr[k] = c.x; wr[k + 1] = c.y; wr[k + 2] = c.z; wr[k + 3] = c.w;
    }
    float bj = bl[j];

    int stride = gridDim.x * 16;
    float hv[4], av[4];
#pragma unroll
    for (int q = 0; q < 4; q++) {
        int i = blockIdx.x * 16 + g + q * 4;
        if (i < n) { hv[q] = h[i * DD + j]; av[q] = agg[i * DD + j]; }
        else       { hv[q] = 0.f; av[q] = 0.f; }
    }
    int buf = 0;
    for (int base = blockIdx.x * 16; base < n; base += stride) {
#pragma unroll
        for (int q = 0; q < 4; q++) {
            sh[buf][g + q * 4][j] = hv[q];
            sa[buf][g + q * 4][j] = av[q];
        }
        __syncthreads();
#pragma unroll
        for (int q = 0; q < 4; q++) {
            int i = base + g + q * 4 + stride;
            if (i < n) { hv[q] = h[i * DD + j]; av[q] = agg[i * DD + j]; }
            else       { hv[q] = 0.f; av[q] = 0.f; }
        }

        float acc[4][4];
#pragma unroll
        for (int q = 0; q < 4; q++)
#pragma unroll
            for (int r = 0; r < 4; r++) acc[q][r] = 0.f;

#pragma unroll
        for (int k4 = 0; k4 < 16; k4++) {
            float w0 = wl[k4 * 4 + 0], w1 = wl[k4 * 4 + 1];
            float w2 = wl[k4 * 4 + 2], w3 = wl[k4 * 4 + 3];
            float r0 = wr[k4 * 4 + 0], r1 = wr[k4 * 4 + 1];
            float r2 = wr[k4 * 4 + 2], r3 = wr[k4 * 4 + 3];
#pragma unroll
            for (int q = 0; q < 4; q++) {
                float4 A = ((const float4*)sa[buf][g + q * 4])[k4];
                float4 H = ((const float4*)sh[buf][g + q * 4])[k4];
                acc[q][0] += A.x * w0; acc[q][1] += A.y * w1;
                acc[q][2] += A.z * w2; acc[q][3] += A.w * w3;
                acc[q][0] += H.x * r0; acc[q][1] += H.y * r1;
                acc[q][2] += H.z * r2; acc[q][3] += H.w * r3;
            }
        }
#pragma unroll
        for (int q = 0; q < 4; q++) {
            int i = base + g + q * 4;
            if (i < n) {
                float r = (acc[q][0] + acc[q][1]) + (acc[q][2] + acc[q][3]) + bj;
                if (do_relu) r = fmaxf(r, 0.f);
                out[i * DD + j] = r;
            }
        }
        buf ^= 1;
        __syncthreads();
    }
}

// ---------------- edge dot product (warp per edge, float2 lanes) ----------------
__global__ __launch_bounds__(256) void k_edge(
    const float* __restrict__ h, const int* __restrict__ ea,
    const int* __restrict__ eb, float* __restrict__ out, int E) {
    int w = (blockIdx.x * blockDim.x + threadIdx.x) >> 5;
    int lane = threadIdx.x & 31;
    if (w >= E) return;
    int a = ea[w];
    int b = eb[w];
    float2 va = ((const float2*)(h + a * DD))[lane];
    float2 vb = ((const float2*)(h + b * DD))[lane];
    float p = va.x * vb.x + va.y * vb.y;
#pragma unroll
    for (int o = 16; o > 0; o >>= 1) p += __shfl_down_sync(0xffffffffu, p, o);
    if (lane == 0) out[w] = p;
}

// ---------------- launch ----------------
static cudaStream_t s_lin = nullptr;
static cudaEvent_t  s_evF = nullptr;
static cudaEvent_t  s_evJ = nullptr;

extern "C" void kernel_launch(void* const* d_in, const int* in_sizes, int n_in,
                              void* d_out, int out_size) {
    const float* x     = (const float*)d_in[0];
    const int*   ei    = (const int*)d_in[1];
    const int*   eli   = (const int*)d_in[2];
    const float* W_lin = (const float*)d_in[3];
    const float* b_lin = (const float*)d_in[4];
    const float* Wl1   = (const float*)d_in[5];
    const float* bl1   = (const float*)d_in[6];
    const float* Wr1   = (const float*)d_in[7];
    const float* Wl2   = (const float*)d_in[8];
    const float* bl2   = (const float*)d_in[9];
    const float* Wr2   = (const float*)d_in[10];

    int N  = in_sizes[0] / DD;      // 100000
    int E  = in_sizes[1] / 2;       // 1000000
    int EL = in_sizes[2] / 2;       // 200000

    const int* src = ei;            // edge_index[0] = source
    const int* dst = ei + E;        // edge_index[1] = target
    const int* ea  = eli;
    const int* eb  = eli + EL;

    float *h0, *h1, *agg;
    int *deg, *rowptr, *cursor, *col, *part, *boff;
    cudaGetSymbolAddress((void**)&h0, g_h0);
    cudaGetSymbolAddress((void**)&h1, g_h1);
    cudaGetSymbolAddress((void**)&agg, g_agg);
    cudaGetSymbolAddress((void**)&deg, g_deg);
    cudaGetSymbolAddress((void**)&rowptr, g_rowptr);
    cudaGetSymbolAddress((void**)&cursor, g_cursor);
    cudaGetSymbolAddress((void**)&col, g_col);
    cudaGetSymbolAddress((void**)&part, g_part);
    cudaGetSymbolAddress((void**)&boff, g_boff);

    float* preds = (float*)d_out;

    // One-time stream/event creation (first call is the uncaptured correctness
    // run, so no resource creation happens during graph capture).
    if (s_lin == nullptr) {
        cudaStreamCreateWithFlags(&s_lin, cudaStreamNonBlocking);
        cudaEventCreateWithFlags(&s_evF, cudaEventDisableTiming);
        cudaEventCreateWithFlags(&s_evJ, cudaEventDisableTiming);
    }

    int nblk = (N + SCAN_CHUNK - 1) / SCAN_CHUNK;   // 196 <= 256

    // Fork: node_lin runs on side stream, overlapped with CSR build.
    cudaEventRecord(s_evF, 0);
    cudaStreamWaitEvent(s_lin, s_evF, 0);
    k_lin<<<296, 256, 0, s_lin>>>(x, W_lin, b_lin, h0, N);
    cudaEventRecord(s_evJ, s_lin);

    // CSR build on the main (captured) stream.
    cudaMemsetAsync(deg, 0, N * sizeof(int), 0);
    k_hist<<<2048, 256>>>(dst, deg, E);
    k_scan1<<<nblk, 256>>>(deg, part, N);
    k_scan2<<<1, 256>>>(part, boff, rowptr, N, nblk);
    k_scan3<<<nblk, 256>>>(deg, boff, rowptr, cursor, N);
    k_scatter<<<2048, 256>>>(src, dst, cursor, col, E);

    // Join: aggregation needs both h0 (lin) and CSR.
    cudaStreamWaitEvent(0, s_evJ, 0);

    // conv1 (relu)
    int agg_blocks = (N * 16 + 255) / 256;
    k_agg<<<agg_blocks, 256>>>(h0, rowptr, col, agg, N);
    k_gemm<<<148, 256>>>(h0, agg, Wl1, bl1, Wr1, h1, N, 1);

    // conv2 (no relu; reuse h0 as output buffer)
    k_agg<<<agg_blocks, 256>>>(h1, rowptr, col, agg, N);
    k_gemm<<<148, 256>>>(h1, agg, Wl2, bl2, Wr2, h0, N, 0);

    // edge classifier
    int blocks = (EL * 32 + 255) / 256;
    k_edge<<<blocks, 256>>>(h0, ea, eb, preds, EL);
}

// round 8
// speedup vs baseline: 1.7952x; 1.5112x over previous
#include <cuda_runtime.h>
#include <cuda_bf16.h>

#define NN 100000
#define DD 64
#define EMAX 1000000
#define SCAN_CHUNK 512   // blocks = ceil(NN/512) = 196 <= 256

typedef unsigned long long u64;

// ---------------- f32x2 packed math (Blackwell sm_103a) ----------------
__device__ __forceinline__ u64 fma2(u64 a, u64 b, u64 c) {
    u64 d;
    asm("fma.rn.f32x2 %0, %1, %2, %3;" : "=l"(d) : "l"(a), "l"(b), "l"(c));
    return d;
}
__device__ __forceinline__ u64 add2(u64 a, u64 b) {
    u64 d;
    asm("add.rn.f32x2 %0, %1, %2;" : "=l"(d) : "l"(a), "l"(b));
    return d;
}
__device__ __forceinline__ u64 mul2(u64 a, u64 b) {
    u64 d;
    asm("mul.rn.f32x2 %0, %1, %2;" : "=l"(d) : "l"(a), "l"(b));
    return d;
}
__device__ __forceinline__ float lo32(u64 a) { return __uint_as_float((unsigned)a); }
__device__ __forceinline__ float hi32(u64 a) { return __uint_as_float((unsigned)(a >> 32)); }

// ---------------- device scratch (no allocation allowed) ----------------
__device__ float g_h0[NN * DD];
__device__ float g_h1[NN * DD];
__device__ float g_agg[NN * DD];
__device__ int   g_deg[NN];
__device__ int   g_rowptr[NN + 1];
__device__ int   g_cursor[NN];
__device__ int   g_col[EMAX];
__device__ u64   g_scan_state[256];   // memset to 0 each launch

// ---------------- CSR build ----------------
__global__ void k_hist(const int* __restrict__ dst, int* __restrict__ deg, int E) {
    for (int e = blockIdx.x * blockDim.x + threadIdx.x; e < E; e += gridDim.x * blockDim.x)
        atomicAdd(&deg[dst[e]], 1);
}

// single-pass decoupled-lookback exclusive scan: deg -> rowptr/cursor
// state word: (value << 2) | flag   flag: 1=aggregate, 2=inclusive prefix
__global__ void k_scan(const int* __restrict__ deg, int* __restrict__ rowptr,
                       int* __restrict__ cursor, u64* __restrict__ state,
                       int n, int nblk) {
    __shared__ int ps[256];
    __shared__ int s_ex;
    int b = blockIdx.x;
    int t = threadIdx.x;
    int base = b * SCAN_CHUNK + t * 2;
    int d0 = (base < n) ? deg[base] : 0;
    int d1 = (base + 1 < n) ? deg[base + 1] : 0;
    ps[t] = d0 + d1;
    __syncthreads();
    for (int d = 1; d < 256; d <<= 1) {
        int v = (t >= d) ? ps[t - d] : 0;
        __syncthreads();
        ps[t] += v;
        __syncthreads();
    }
    int total = ps[255];

    if (t == 0) {
        if (b == 0) {
            atomicExch(&state[0], ((u64)total << 2) | 2ULL);
            s_ex = 0;
        } else {
            atomicExch(&state[b], ((u64)total << 2) | 1ULL);
            int ex = 0;
            int p = b - 1;
            while (true) {
                u64 s;
                do {
                    s = *(volatile u64*)&state[p];
                } while ((s & 3ULL) == 0ULL);
                int v = (int)(s >> 2);
                ex += v;
                if ((s & 3ULL) == 2ULL) break;
                p--;
            }
            atomicExch(&state[b], ((u64)(ex + total) << 2) | 2ULL);
            s_ex = ex;
        }
    }
    __syncthreads();
    int off = s_ex + ps[t] - (d0 + d1);
    if (base < n)     { rowptr[base] = off;          cursor[base] = off; }
    if (base + 1 < n) { rowptr[base + 1] = off + d0; cursor[base + 1] = off + d0; }
    if (b == nblk - 1 && t == 255) rowptr[n] = s_ex + total;
}

__global__ void k_scatter(const int* __restrict__ src, const int* __restrict__ dst,
                          int* __restrict__ cursor, int* __restrict__ col, int E) {
    for (int e = blockIdx.x * blockDim.x + threadIdx.x; e < E; e += gridDim.x * blockDim.x) {
        int d = dst[e];
        int p = atomicAdd(&cursor[d], 1);
        col[p] = src[e];
    }
}

// ---------------- mean aggregation: half-warp per node, packed f32x2 ----------------
__global__ __launch_bounds__(256) void k_agg(
    const float* __restrict__ h, const int* __restrict__ rowptr,
    const int* __restrict__ col, float* __restrict__ agg, int n) {
    int node = (blockIdx.x * blockDim.x + threadIdx.x) >> 4;
    int l = threadIdx.x & 15;
    if (node >= n) return;
    int s = rowptr[node];
    int e = rowptr[node + 1];
    u64 axy = 0ULL, azw = 0ULL;
    int nn = s;
    for (; nn + 8 <= e; nn += 8) {
        int c0 = col[nn],     c1 = col[nn + 1], c2 = col[nn + 2], c3 = col[nn + 3];
        int c4 = col[nn + 4], c5 = col[nn + 5], c6 = col[nn + 6], c7 = col[nn + 7];
        ulonglong2 v0 = ((const ulonglong2*)(h + c0 * DD))[l];
        ulonglong2 v1 = ((const ulonglong2*)(h + c1 * DD))[l];
        ulonglong2 v2 = ((const ulonglong2*)(h + c2 * DD))[l];
        ulonglong2 v3 = ((const ulonglong2*)(h + c3 * DD))[l];
        ulonglong2 v4 = ((const ulonglong2*)(h + c4 * DD))[l];
        ulonglong2 v5 = ((const ulonglong2*)(h + c5 * DD))[l];
        ulonglong2 v6 = ((const ulonglong2*)(h + c6 * DD))[l];
        ulonglong2 v7 = ((const ulonglong2*)(h + c7 * DD))[l];
        u64 p0 = add2(add2(v0.x, v1.x), add2(v2.x, v3.x));
        u64 p1 = add2(add2(v4.x, v5.x), add2(v6.x, v7.x));
        u64 q0 = add2(add2(v0.y, v1.y), add2(v2.y, v3.y));
        u64 q1 = add2(add2(v4.y, v5.y), add2(v6.y, v7.y));
        axy = add2(axy, add2(p0, p1));
        azw = add2(azw, add2(q0, q1));
    }
    for (; nn + 4 <= e; nn += 4) {
        int c0 = col[nn], c1 = col[nn + 1], c2 = col[nn + 2], c3 = col[nn + 3];
        ulonglong2 v0 = ((const ulonglong2*)(h + c0 * DD))[l];
        ulonglong2 v1 = ((const ulonglong2*)(h + c1 * DD))[l];
        ulonglong2 v2 = ((const ulonglong2*)(h + c2 * DD))[l];
        ulonglong2 v3 = ((const ulonglong2*)(h + c3 * DD))[l];
        axy = add2(axy, add2(add2(v0.x, v1.x), add2(v2.x, v3.x)));
        azw = add2(azw, add2(add2(v0.y, v1.y), add2(v2.y, v3.y)));
    }
    for (; nn < e; nn++) {
        ulonglong2 v = ((const ulonglong2*)(h + col[nn] * DD))[l];
        axy = add2(axy, v.x);
        azw = add2(azw, v.y);
    }
    float inv = (e > s) ? 1.f / (float)(e - s) : 0.f;
    unsigned ui = __float_as_uint(inv);
    u64 inv2 = ((u64)ui << 32) | ui;
    ((ulonglong2*)(agg + node * DD))[l] = make_ulonglong2(mul2(axy, inv2), mul2(azw, inv2));
}

// ---------------- node linear: out = x @ W^T + b (f32x2, double-buffered) ----------------
__global__ __launch_bounds__(256, 2) void k_lin(
    const float* __restrict__ x, const float* __restrict__ W,
    const float* __restrict__ b, float* __restrict__ out, int n) {
    __shared__ __align__(16) float sh[2][4][DD];
    int tid = threadIdx.x;
    int g = tid >> 6;
    int j = tid & 63;

    u64 w2[32];
#pragma unroll
    for (int k = 0; k < 32; k += 2) {
        ulonglong2 a = *(const ulonglong2*)&W[j * DD + k * 2];
        w2[k] = a.x;
        w2[k + 1] = a.y;
    }
    float bj = b[j];

    int stride = gridDim.x * 4;
    int i0 = blockIdx.x * 4 + g;
    float hv = (i0 < n) ? x[i0 * DD + j] : 0.f;
    int buf = 0;
    for (int base = blockIdx.x * 4; base < n; base += stride) {
        int i = base + g;
        sh[buf][g][j] = hv;
        __syncthreads();
        int inx = i + stride;
        hv = (inx < n) ? x[inx * DD + j] : 0.f;
        if (i < n) {
            const ulonglong2* h2 = (const ulonglong2*)sh[buf][g];
            u64 acc0 = 0ULL, acc1 = 0ULL;
#pragma unroll
            for (int k4 = 0; k4 < 16; k4++) {
                ulonglong2 H = h2[k4];
                acc0 = fma2(H.x, w2[2 * k4], acc0);
                acc1 = fma2(H.y, w2[2 * k4 + 1], acc1);
            }
            out[i * DD + j] = (lo32(acc0) + hi32(acc0)) + (lo32(acc1) + hi32(acc1)) + bj;
        }
        buf ^= 1;
    }
}

// ---------------- dense SAGE transform: out = agg@Wl^T + bl + h@Wr^T (f32x2) ----------------
// 8 nodes per block-iteration; each thread computes col j for 2 nodes.
__global__ __launch_bounds__(256, 1) void k_gemm(
    const float* __restrict__ h, const float* __restrict__ agg,
    const float* __restrict__ Wl, const float* __restrict__ bl,
    const float* __restrict__ Wr, float* __restrict__ out, int n, int do_relu) {
    __shared__ __align__(16) float sh[2][8][DD];
    __shared__ __align__(16) float sa[2][8][DD];
    int tid = threadIdx.x;
    int g = tid >> 6;       // 0..3
    int j = tid & 63;

    u64 wl2[32], wr2[32];
#pragma unroll
    for (int k = 0; k < 32; k += 2) {
        ulonglong2 a = *(const ulonglong2*)&Wl[j * DD + k * 2];
        wl2[k] = a.x; wl2[k + 1] = a.y;
        ulonglong2 c = *(const ulonglong2*)&Wr[j * DD + k * 2];
        wr2[k] = c.x; wr2[k + 1] = c.y;
    }
    float bj = bl[j];

    int stride = gridDim.x * 8;
    int iA0 = blockIdx.x * 8 + g;
    int iB0 = iA0 + 4;
    float hvA = 0.f, avA = 0.f, hvB = 0.f, avB = 0.f;
    if (iA0 < n) { hvA = h[iA0 * DD + j]; avA = agg[iA0 * DD + j]; }
    if (iB0 < n) { hvB = h[iB0 * DD + j]; avB = agg[iB0 * DD + j]; }
    int buf = 0;
    for (int base = blockIdx.x * 8; base < n; base += stride) {
        int iA = base + g;
        int iB = iA + 4;
        sh[buf][g][j] = hvA;
        sa[buf][g][j] = avA;
        sh[buf][g + 4][j] = hvB;
        sa[buf][g + 4][j] = avB;
        __syncthreads();
        int nA = iA + stride, nB = iB + stride;
        if (nA < n) { hvA = h[nA * DD + j]; avA = agg[nA * DD + j]; }
        else        { hvA = 0.f; avA = 0.f; }
        if (nB < n) { hvB = h[nB * DD + j]; avB = agg[nB * DD + j]; }
        else        { hvB = 0.f; avB = 0.f; }

        const ulonglong2* hA = (const ulonglong2*)sh[buf][g];
        const ulonglong2* aA = (const ulonglong2*)sa[buf][g];
        const ulonglong2* hB = (const ulonglong2*)sh[buf][g + 4];
        const ulonglong2* aB = (const ulonglong2*)sa[buf][g + 4];
        u64 accA0 = 0ULL, accA1 = 0ULL, accB0 = 0ULL, accB1 = 0ULL;
#pragma unroll
        for (int k4 = 0; k4 < 16; k4++) {
            ulonglong2 Aa = aA[k4];
            ulonglong2 Ha = hA[k4];
            ulonglong2 Ab = aB[k4];
            ulonglong2 Hb = hB[k4];
            u64 wlo = wl2[2 * k4], whi = wl2[2 * k4 + 1];
            u64 rlo = wr2[2 * k4], rhi = wr2[2 * k4 + 1];
            accA0 = fma2(Aa.x, wlo, accA0);
            accA1 = fma2(Aa.y, whi, accA1);
            accA0 = fma2(Ha.x, rlo, accA0);
            accA1 = fma2(Ha.y, rhi, accA1);
            accB0 = fma2(Ab.x, wlo, accB0);
            accB1 = fma2(Ab.y, whi, accB1);
            accB0 = fma2(Hb.x, rlo, accB0);
            accB1 = fma2(Hb.y, rhi, accB1);
        }
        if (iA < n) {
            float r = (lo32(accA0) + hi32(accA0)) + (lo32(accA1) + hi32(accA1)) + bj;
            if (do_relu) r = fmaxf(r, 0.f);
            out[iA * DD + j] = r;
        }
        if (iB < n) {
            float r = (lo32(accB0) + hi32(accB0)) + (lo32(accB1) + hi32(accB1)) + bj;
            if (do_relu) r = fmaxf(r, 0.f);
            out[iB * DD + j] = r;
        }
        buf ^= 1;
        __syncthreads();
    }
}

// ---------------- edge dot product (warp per edge, float2 lanes) ----------------
__global__ __launch_bounds__(256) void k_edge(
    const float* __restrict__ h, const int* __restrict__ ea,
    const int* __restrict__ eb, float* __restrict__ out, int E) {
    int w = (blockIdx.x * blockDim.x + threadIdx.x) >> 5;
    int lane = threadIdx.x & 31;
    if (w >= E) return;
    int a = ea[w];
    int b = eb[w];
    float2 va = ((const float2*)(h + a * DD))[lane];
    float2 vb = ((const float2*)(h + b * DD))[lane];
    float p = va.x * vb.x + va.y * vb.y;
#pragma unroll
    for (int o = 16; o > 0; o >>= 1) p += __shfl_down_sync(0xffffffffu, p, o);
    if (lane == 0) out[w] = p;
}

// ---------------- launch ----------------
static cudaStream_t s_lin = nullptr;
static cudaEvent_t  s_evF = nullptr;
static cudaEvent_t  s_evJ = nullptr;

extern "C" void kernel_launch(void* const* d_in, const int* in_sizes, int n_in,
                              void* d_out, int out_size) {
    const float* x     = (const float*)d_in[0];
    const int*   ei    = (const int*)d_in[1];
    const int*   eli   = (const int*)d_in[2];
    const float* W_lin = (const float*)d_in[3];
    const float* b_lin = (const float*)d_in[4];
    const float* Wl1   = (const float*)d_in[5];
    const float* bl1   = (const float*)d_in[6];
    const float* Wr1   = (const float*)d_in[7];
    const float* Wl2   = (const float*)d_in[8];
    const float* bl2   = (const float*)d_in[9];
    const float* Wr2   = (const float*)d_in[10];

    int N  = in_sizes[0] / DD;      // 100000
    int E  = in_sizes[1] / 2;       // 1000000
    int EL = in_sizes[2] / 2;       // 200000

    const int* src = ei;            // edge_index[0] = source
    const int* dst = ei + E;        // edge_index[1] = target
    const int* ea  = eli;
    const int* eb  = eli + EL;

    float *h0, *h1, *agg;
    int *deg, *rowptr, *cursor, *col;
    u64 *state;
    cudaGetSymbolAddress((void**)&h0, g_h0);
    cudaGetSymbolAddress((void**)&h1, g_h1);
    cudaGetSymbolAddress((void**)&agg, g_agg);
    cudaGetSymbolAddress((void**)&deg, g_deg);
    cudaGetSymbolAddress((void**)&rowptr, g_rowptr);
    cudaGetSymbolAddress((void**)&cursor, g_cursor);
    cudaGetSymbolAddress((void**)&col, g_col);
    cudaGetSymbolAddress((void**)&state, g_scan_state);

    float* preds = (float*)d_out;

    // One-time stream/event creation (first call is the uncaptured correctness
    // run, so no resource creation happens during graph capture).
    if (s_lin == nullptr) {
        cudaStreamCreateWithFlags(&s_lin, cudaStreamNonBlocking);
        cudaEventCreateWithFlags(&s_evF, cudaEventDisableTiming);
        cudaEventCreateWithFlags(&s_evJ, cudaEventDisableTiming);
    }

    int nblk = (N + SCAN_CHUNK - 1) / SCAN_CHUNK;   // 196 <= 256

    // Fork: node_lin runs on side stream, overlapped with CSR build.
    cudaEventRecord(s_evF, 0);
    cudaStreamWaitEvent(s_lin, s_evF, 0);
    k_lin<<<296, 256, 0, s_lin>>>(x, W_lin, b_lin, h0, N);
    cudaEventRecord(s_evJ, s_lin);

    // CSR build on the main (captured) stream.
    cudaMemsetAsync(deg, 0, N * sizeof(int), 0);
    cudaMemsetAsync(state, 0, 256 * sizeof(u64), 0);
    k_hist<<<2048, 256>>>(dst, deg, E);
    k_scan<<<nblk, 256>>>(deg, rowptr, cursor, state, N, nblk);
    k_scatter<<<2048, 256>>>(src, dst, cursor, col, E);

    // Join: aggregation needs both h0 (lin) and CSR.
    cudaStreamWaitEvent(0, s_evJ, 0);

    // conv1 (relu)
    int agg_blocks = (N * 16 + 255) / 256;
    k_agg<<<agg_blocks, 256>>>(h0, rowptr, col, agg, N);
    k_gemm<<<148, 256>>>(h0, agg, Wl1, bl1, Wr1, h1, N, 1);

    // conv2 (no relu; reuse h0 as output buffer)
    k_agg<<<agg_blocks, 256>>>(h1, rowptr, col, agg, N);
    k_gemm<<<148, 256>>>(h1, agg, Wl2, bl2, Wr2, h0, N, 0);

    // edge classifier
    int blocks = (EL * 32 + 255) / 256;
    k_edge<<<blocks, 256>>>(h0, ea, eb, preds, EL);
}